// round 16
// baseline (speedup 1.0000x reference)
#include <cuda_runtime.h>
#include <cuda_bf16.h>

// out[b] = bias + sum_{t in unique(text[:, b])} W[t]
//   text: [L=200, B=4096] int32 row-major, values in [0, 50000)
//   W:    [50000] float32, b: [1] float32, out: [B, 1] float32
//
// 8 docs per block (256 threads), per-doc shared bitset (1563 words).
// Latency-optimized: prefetch all tokens behind smem zeroing, then issue all
// W gathers + all shared atomicOrs with full MLP, then predicated adds.
// Thread t -> doc (t&7), row base tid>>3, rows stride 32 -> 32B coalesced
// segments (4 sectors per warp load).

#define L_SEQ 200
#define BATCH 4096
#define VOCAB 50000
#define DOCS_PER_BLOCK 8
#define THREADS 256
#define TOK_MAX 7                               // ceil(1600/256)
#define BITMAP_WORDS 1564                       // ceil(50000/32)=1563, pad %4==0
#define SMEM_WORDS (DOCS_PER_BLOCK * BITMAP_WORDS)
#define SMEM_BYTES (SMEM_WORDS * 4 + DOCS_PER_BLOCK * 4)

__global__ void __launch_bounds__(THREADS, 4)
doc_presence_dot_kernel(const int* __restrict__ text,
                        const float* __restrict__ W,
                        const float* __restrict__ bias,
                        float* __restrict__ out)
{
    extern __shared__ unsigned smem[];
    unsigned* bitmap = smem;                        // [8][BITMAP_WORDS]
    float* acc = (float*)(smem + SMEM_WORDS);       // [8]

    const int tid    = threadIdx.x;
    const int doc    = tid & 7;
    const int b0     = blockIdx.x * DOCS_PER_BLOCK;
    const int base_l = tid >> 3;                    // 0..31

    // ---- Phase 1: prefetch tokens (MLP=7), overlapped with smem zeroing ----
    int t[TOK_MAX];
    #pragma unroll
    for (int k = 0; k < TOK_MAX; k++) {
        const int l = base_l + 32 * k;
        if (l < L_SEQ)
            t[k] = text[l * BATCH + b0 + doc];
    }

    {
        uint4 z = make_uint4(0u, 0u, 0u, 0u);
        uint4* p = (uint4*)smem;
        #pragma unroll
        for (int i = tid; i < SMEM_WORDS / 4; i += THREADS)
            p[i] = z;
        if (tid < DOCS_PER_BLOCK) acc[tid] = 0.0f;
    }
    __syncthreads();

    // ---- Phase 2: batched W gathers (address dep only on t, not atomics) ----
    float w[TOK_MAX];
    #pragma unroll
    for (int k = 0; k < TOK_MAX; k++) {
        const int l = base_l + 32 * k;
        if (l < L_SEQ)
            w[k] = __ldg(&W[t[k]]);
    }

    // ---- Phase 3: batched first-occurrence tests ----
    unsigned old[TOK_MAX];
    unsigned* my_bitmap = bitmap + doc * BITMAP_WORDS;
    #pragma unroll
    for (int k = 0; k < TOK_MAX; k++) {
        const int l = base_l + 32 * k;
        if (l < L_SEQ)
            old[k] = atomicOr(&my_bitmap[t[k] >> 5], 1u << (t[k] & 31));
    }

    // ---- Phase 4: predicated accumulation ----
    float sum = 0.0f;
    #pragma unroll
    for (int k = 0; k < TOK_MAX; k++) {
        const int l = base_l + 32 * k;
        if (l < L_SEQ && !(old[k] & (1u << (t[k] & 31))))
            sum += w[k];
    }

    // Reduce lanes sharing a doc (lane, lane^8, lane^16)
    sum += __shfl_xor_sync(0xffffffffu, sum, 8);
    sum += __shfl_xor_sync(0xffffffffu, sum, 16);
    if ((tid & 31) < DOCS_PER_BLOCK)
        atomicAdd(&acc[doc], sum);
    __syncthreads();

    if (tid < DOCS_PER_BLOCK)
        out[b0 + tid] = acc[tid] + bias[0];
}

extern "C" void kernel_launch(void* const* d_in, const int* in_sizes, int n_in,
                              void* d_out, int out_size)
{
    const int*   text = (const int*)d_in[0];
    const float* W    = (const float*)d_in[1];
    const float* bias = (const float*)d_in[2];
    float*       out  = (float*)d_out;

    (void)in_sizes; (void)n_in; (void)out_size;

    static bool attr_set = false;
    if (!attr_set) {
        cudaFuncSetAttribute(doc_presence_dot_kernel,
                             cudaFuncAttributeMaxDynamicSharedMemorySize, SMEM_BYTES);
        attr_set = true;
    }

    dim3 grid(BATCH / DOCS_PER_BLOCK);  // 512 blocks, ~1 wave at 4 blocks/SM
    doc_presence_dot_kernel<<<grid, THREADS, SMEM_BYTES>>>(text, W, bias, out);
}

// round 17
// speedup vs baseline: 1.0226x; 1.0226x over previous
#include <cuda_runtime.h>
#include <cuda_bf16.h>

// out[b] = bias + sum_{t in unique(text[:, b])} W[t]
//   text: [L=200, B=4096] int32 row-major, values in [0, 50000)
//   W:    [50000] float32, b: [1] float32, out: [B, 1] float32
//
// 4 docs per block, 256 threads, 25 KB smem bitset per block ->
// 8 blocks/SM -> ~100% occupancy (vs 42% with 8-doc blocks).
// Thread t -> doc (t&3), rows l = (t>>2) + 64k (k<4). 4 adjacent lanes read
// 4 consecutive int32 of one text row -> 16B segments, coalesced per warp.
// atomicOr old-value gives first-occurrence; W gathered unconditionally
// (address dep only on token), predicated add.

#define L_SEQ 200
#define BATCH 4096
#define VOCAB 50000
#define DOCS_PER_BLOCK 4
#define THREADS 256
#define TOK_MAX 4                               // rows per thread: l = base_l + 64k
#define BITMAP_WORDS 1564                       // ceil(50000/32)=1563, pad %4==0
#define SMEM_WORDS (DOCS_PER_BLOCK * BITMAP_WORDS)   // 6256 words = 25024 B
#define SMEM_BYTES (SMEM_WORDS * 4 + DOCS_PER_BLOCK * 4)

__global__ void __launch_bounds__(THREADS, 8)
doc_presence_dot_kernel(const int* __restrict__ text,
                        const float* __restrict__ W,
                        const float* __restrict__ bias,
                        float* __restrict__ out)
{
    extern __shared__ unsigned smem[];
    unsigned* bitmap = smem;                        // [4][BITMAP_WORDS]
    float* acc = (float*)(smem + SMEM_WORDS);       // [4]

    const int tid    = threadIdx.x;
    const int doc    = tid & 3;
    const int b0     = blockIdx.x * DOCS_PER_BLOCK;
    const int base_l = tid >> 2;                    // 0..63

    // ---- Phase 1: prefetch tokens (overlaps smem zeroing) ----
    int t[TOK_MAX];
    #pragma unroll
    for (int k = 0; k < TOK_MAX; k++) {
        const int l = base_l + 64 * k;              // k<3 always valid; k=3 iff base_l<8
        if (l < L_SEQ)
            t[k] = text[l * BATCH + b0 + doc];
    }

    // ---- W gathers issued early too: address dep only on t ----
    float w[TOK_MAX];
    #pragma unroll
    for (int k = 0; k < TOK_MAX; k++) {
        const int l = base_l + 64 * k;
        if (l < L_SEQ)
            w[k] = __ldg(&W[t[k]]);
    }

    // ---- Zero bitmaps (1564 uint4 across 256 threads) ----
    {
        uint4 z = make_uint4(0u, 0u, 0u, 0u);
        uint4* p = (uint4*)smem;
        #pragma unroll
        for (int i = tid; i < SMEM_WORDS / 4; i += THREADS)
            p[i] = z;
        if (tid < DOCS_PER_BLOCK) acc[tid] = 0.0f;
    }
    __syncthreads();

    // ---- First-occurrence tests (batched) ----
    unsigned old[TOK_MAX];
    unsigned* my_bitmap = bitmap + doc * BITMAP_WORDS;
    #pragma unroll
    for (int k = 0; k < TOK_MAX; k++) {
        const int l = base_l + 64 * k;
        if (l < L_SEQ)
            old[k] = atomicOr(&my_bitmap[t[k] >> 5], 1u << (t[k] & 31));
    }

    // ---- Predicated accumulation ----
    float sum = 0.0f;
    #pragma unroll
    for (int k = 0; k < TOK_MAX; k++) {
        const int l = base_l + 64 * k;
        if (l < L_SEQ && !(old[k] & (1u << (t[k] & 31))))
            sum += w[k];
    }

    // Reduce lanes sharing a doc: lanes doc, doc+4, ..., doc+28
    sum += __shfl_xor_sync(0xffffffffu, sum, 4);
    sum += __shfl_xor_sync(0xffffffffu, sum, 8);
    sum += __shfl_xor_sync(0xffffffffu, sum, 16);
    if ((tid & 31) < DOCS_PER_BLOCK)
        atomicAdd(&acc[doc], sum);
    __syncthreads();

    if (tid < DOCS_PER_BLOCK)
        out[b0 + tid] = acc[tid] + bias[0];
}

extern "C" void kernel_launch(void* const* d_in, const int* in_sizes, int n_in,
                              void* d_out, int out_size)
{
    const int*   text = (const int*)d_in[0];
    const float* W    = (const float*)d_in[1];
    const float* bias = (const float*)d_in[2];
    float*       out  = (float*)d_out;

    (void)in_sizes; (void)n_in; (void)out_size;

    static bool attr_set = false;
    if (!attr_set) {
        cudaFuncSetAttribute(doc_presence_dot_kernel,
                             cudaFuncAttributeMaxDynamicSharedMemorySize, SMEM_BYTES);
        attr_set = true;
    }

    dim3 grid(BATCH / DOCS_PER_BLOCK);  // 1024 blocks, 8/SM, ~1 wave
    doc_presence_dot_kernel<<<grid, THREADS, SMEM_BYTES>>>(text, W, bias, out);
}